// round 13
// baseline (speedup 1.0000x reference)
#include <cuda_runtime.h>
#include <math.h>

// Fixed-shape problem: N=16384, D=8, pid in [0,2000), K=128, R=1
#define NMAX    16384
#define NPIDMAX 2048
#define KSEL2   129     // top-(K+1) including self (self weight = 0)
#define CPT     4       // condensation points per repulsion block
#define RT      256     // threads per block
#define NW      (RT/32) // warps per block
#define NBINS   258     // bins over scaled D2=256*d2
#define CAPW    128     // per-warp candidate segment capacity
#define SMIN    48      // sampled-cum threshold (1/8 sampling)

// -------- device scratch (small, allocation-free) --------
__device__ unsigned long long g_best[NPIDMAX];
__device__ float  g_q[NMAX];
__device__ float  g_n2[NMAX];
__device__ float4 g_xp[NMAX * 2];
__device__ int    g_cplist[NPIDMAX];
__device__ int    g_cpcount;
__device__ double g_att;
__device__ double g_rep;
__device__ int    g_maskcnt;

// predicated shared histogram increment (R9-proven light form)
__device__ __forceinline__ void hist_add(unsigned smem_addr, float D2) {
    asm volatile(
        "{\n\t.reg .pred p;\n\t"
        "setp.le.f32 p, %1, 0f43800000;\n\t"   // D2 <= 256.0f
        "@p red.shared.add.u32 [%0], 1;\n\t}"
        :: "r"(smem_addr), "f"(D2) : "memory");
}

__global__ void k_init() {
    int i = blockIdx.x * blockDim.x + threadIdx.x;
    if (i < NPIDMAX) g_best[i] = 0ULL;
    if (i == 0) { g_cpcount = 0; g_att = 0.0; g_rep = 0.0; g_maskcnt = 0; }
}

__global__ void k_bestq(const float* __restrict__ beta, const int* __restrict__ pid,
                        const float* __restrict__ x, int N) {
    int i = blockIdx.x * blockDim.x + threadIdx.x;
    if (i >= N) return;
    float b = beta[i];
    float t = atanhf(b);
    g_q[i] = t * t + 0.01f;
    float4 v0 = *(const float4*)(x + (size_t)i * 8);
    float4 v1 = *(const float4*)(x + (size_t)i * 8 + 4);
    float n2 = v0.x * v0.x + v0.y * v0.y + v0.z * v0.z + v0.w * v0.w
             + v1.x * v1.x + v1.y * v1.y + v1.z * v1.z + v1.w * v1.w;
    g_n2[i] = n2;
    g_xp[2 * i + 0] = v0;
    g_xp[2 * i + 1] = v1;
    int p = pid[i];
    if (p > 0 && p < NPIDMAX) {
        unsigned long long key =
            ((unsigned long long)__float_as_uint(b) << 32) |
            (unsigned long long)(0xFFFFFFFFu - (unsigned)i);
        atomicMax(&g_best[p], key);
    }
}

__global__ void k_attract(const float* __restrict__ x, const int* __restrict__ pid,
                          const int* __restrict__ recon, const float* __restrict__ pt,
                          const float* __restrict__ eta, int N) {
    int i = blockIdx.x * blockDim.x + threadIdx.x;
    if (i > 0 && i < NPIDMAX) {
        unsigned long long key = g_best[i];
        if (key != 0ULL) {
            int idx = (int)(0xFFFFFFFFu - (unsigned)(key & 0xFFFFFFFFull));
            int pos = atomicAdd(&g_cpcount, 1);
            g_cplist[pos] = idx;
        }
    }
    float va = 0.0f; int m = 0;
    if (i < N) {
        int p = pid[i];
        if (p > 0 && pt[i] > 0.9f && recon[i] > 0 && fabsf(eta[i]) < 4.0f) {
            unsigned long long key = g_best[p];
            int a = (int)(0xFFFFFFFFu - (unsigned)(key & 0xFFFFFFFFull));
            const float4* xi = (const float4*)(x + (size_t)i * 8);
            const float4* xa = (const float4*)(x + (size_t)a * 8);
            float4 i0 = xi[0], i1 = xi[1], a0 = xa[0], a1 = xa[1];
            float d, d2 = 0.0f;
            d = i0.x - a0.x; d2 += d * d;
            d = i0.y - a0.y; d2 += d * d;
            d = i0.z - a0.z; d2 += d * d;
            d = i0.w - a0.w; d2 += d * d;
            d = i1.x - a1.x; d2 += d * d;
            d = i1.y - a1.y; d2 += d * d;
            d = i1.z - a1.z; d2 += d * d;
            d = i1.w - a1.w; d2 += d * d;
            va = d2 * g_q[i] * g_q[a];
            m = 1;
        }
    }
    #pragma unroll
    for (int o = 16; o; o >>= 1) {
        va += __shfl_down_sync(0xFFFFFFFFu, va, o);
        m  += __shfl_down_sync(0xFFFFFFFFu, m,  o);
    }
    if ((threadIdx.x & 31) == 0 && (m || va != 0.0f)) {
        atomicAdd(&g_att, (double)va);
        atomicAdd(&g_maskcnt, m);
    }
}

// scaled distance chain: D2 = 256*d2 (m2x = -512*xc, n2cs = 256*|xc|^2)
#define D2_CHAIN(res, V0, V1, N2J, c)                 \
    float res = fmaf(V0.x, m2x[c][0], n2cs[c]);       \
    res = fmaf(V0.y, m2x[c][1], res);                 \
    res = fmaf(V0.z, m2x[c][2], res);                 \
    res = fmaf(V0.w, m2x[c][3], res);                 \
    res = fmaf(V1.x, m2x[c][4], res);                 \
    res = fmaf(V1.y, m2x[c][5], res);                 \
    res = fmaf(V1.z, m2x[c][6], res);                 \
    res = fmaf(N2J, 256.0f, res);                     \
    res = fmaf(V1.w, m2x[c][7], res);

__global__ void __launch_bounds__(RT, 4) k_repulse(const int* __restrict__ pid, int N) {
    __shared__ int      s_hist[CPT][NBINS];
    __shared__ int      s_bj[CPT][NW][CAPW];
    __shared__ unsigned s_bk[CPT][NW][CAPW];
    __shared__ int      s_cnt[CPT][NW];
    __shared__ int      s_ovf[CPT];
    __shared__ float    s_fT[CPT];
    __shared__ float    s_qc[CPT];
    __shared__ int      s_pidc[CPT];
    __shared__ int      s_B2, s_cumb, s_need, s_m, s_bcnt;
    __shared__ float    s_red[NW];

    int tid  = threadIdx.x;
    int wid  = tid >> 5;
    int lane = tid & 31;
    unsigned lml = (1u << lane) - 1u;
    int ncp   = g_cpcount;
    int cbase = blockIdx.x * CPT;
    if (cbase >= ncp) return;

    float m2x[CPT][8], n2cs[CPT];
    #pragma unroll
    for (int c = 0; c < CPT; c++) {
        int slot = cbase + c;
        bool act = slot < ncp;
        int ci = act ? g_cplist[slot] : 0;
        float4 p0 = g_xp[2 * ci + 0];
        float4 p1 = g_xp[2 * ci + 1];
        m2x[c][0] = -512.0f * p0.x; m2x[c][1] = -512.0f * p0.y;
        m2x[c][2] = -512.0f * p0.z; m2x[c][3] = -512.0f * p0.w;
        m2x[c][4] = -512.0f * p1.x; m2x[c][5] = -512.0f * p1.y;
        m2x[c][6] = -512.0f * p1.z; m2x[c][7] = -512.0f * p1.w;
        n2cs[c] = act ? 256.0f * g_n2[ci] : 1e30f;
        if (tid == 0) {
            s_pidc[c] = act ? pid[ci] : -1;
            s_qc[c]   = act ? g_q[ci] : 0.0f;
        }
    }

    for (int h = tid; h < CPT * NBINS; h += RT) ((int*)s_hist)[h] = 0;
    if (tid < CPT) s_ovf[tid] = 0;
    __syncthreads();

    unsigned histb[CPT];
    #pragma unroll
    for (int c = 0; c < CPT; c++)
        histb[c] = (unsigned)__cvta_generic_to_shared(&s_hist[c][0]);

    // ---- Phase S: 1/8-sampled histogram ----
    #pragma unroll
    for (int k = 0; k < 8; k++) {
        int j = (k << 11) + tid;
        float4 a0 = g_xp[2 * j + 0];
        float4 a1 = g_xp[2 * j + 1];
        float n2a = g_n2[j];
        #pragma unroll
        for (int c = 0; c < CPT; c++) {
            D2_CHAIN(D2, a0, a1, n2a, c)
            int bb = min((int)fmaxf(D2, 0.0f), NBINS - 1);
            hist_add(histb[c] + (unsigned)(bb << 2), D2);
        }
    }
    __syncthreads();

    // ---- threshold per CP from sampled hist ----
    if (tid < CPT) {
        int cum = 0, B = 256;
        for (int b = 0; b < 256; b++) {
            cum += s_hist[tid][b];
            if (cum >= SMIN) { B = b; break; }
        }
        s_fT[tid] = (B >= 256) ? 256.0f : (float)(B + 1);
    }
    __syncthreads();
    float fTr[CPT];
    #pragma unroll
    for (int c = 0; c < CPT; c++) fTr[c] = s_fT[c];
    // re-zero hists for reuse in final phase
    for (int h = tid; h < CPT * NBINS; h += RT) ((int*)s_hist)[h] = 0;
    __syncthreads();

    // ---- Phase B: ONE full pass, atomic-free warp-aggregated append ----
    int cnt[CPT];
    #pragma unroll
    for (int c = 0; c < CPT; c++) cnt[c] = 0;

    for (int j = tid; j < N; j += RT) {
        float4 a0 = g_xp[2 * j + 0];
        float4 a1 = g_xp[2 * j + 1];
        float n2a = g_n2[j];
        #pragma unroll
        for (int c = 0; c < CPT; c++) {
            D2_CHAIN(D2, a0, a1, n2a, c)
            bool pr = (D2 <= fTr[c]);
            unsigned bal = __ballot_sync(0xFFFFFFFFu, pr);
            int pos = cnt[c] + __popc(bal & lml);
            if (pr && pos < CAPW) s_bj[c][wid][pos] = j;
            cnt[c] += __popc(bal);
        }
    }
    if (lane == 0) {
        #pragma unroll
        for (int c = 0; c < CPT; c++) {
            s_cnt[c][wid] = min(cnt[c], CAPW);
            if (cnt[c] > CAPW) s_ovf[c] = 1;
        }
    }
    __syncthreads();

    // ---- per-CP finalize (normal path or rare exact fallback) ----
    for (int c = 0; c < CPT; c++) {
        if (tid == 0) {
            int m = 0;
            for (int w = 0; w < NW; w++) m += s_cnt[c][w];
            s_m = m;
            s_need = s_ovf[c] || (m < KSEL2 && s_fT[c] < 256.0f);
            s_bcnt = 0;
        }
        __syncthreads();

        float part = 0.0f;

        if (s_need) {
            // ===== exact fallback for this CP (rare) =====
            for (int h = tid; h < NBINS; h += RT) s_hist[c][h] = 0;
            __syncthreads();
            for (int j = tid; j < N; j += RT) {
                float4 a0 = g_xp[2 * j + 0];
                float4 a1 = g_xp[2 * j + 1];
                float n2a = g_n2[j];
                D2_CHAIN(D2, a0, a1, n2a, c)
                int bb = min((int)fmaxf(D2, 0.0f), NBINS - 1);
                hist_add(histb[c] + (unsigned)(bb << 2), D2);
            }
            __syncthreads();
            if (tid == 0) {
                int cum = 0, B = NBINS, cb = 0;
                for (int b = 0; b < NBINS; b++) {
                    int nc = cum + s_hist[c][b];
                    if (nc >= KSEL2) { B = b; cb = cum; break; }
                    cum = nc;
                }
                s_B2 = B; s_cumb = cb;
            }
            __syncthreads();
            int B2 = s_B2;
            for (int j = tid; j < N; j += RT) {
                float4 a0 = g_xp[2 * j + 0];
                float4 a1 = g_xp[2 * j + 1];
                float n2a = g_n2[j];
                D2_CHAIN(D2, a0, a1, n2a, c)
                if (D2 <= 256.0f) {
                    float Dc = fmaxf(D2, 0.0f);
                    int bb = min((int)Dc, NBINS - 1);
                    if (bb < B2) {
                        if (pid[j] != s_pidc[c])
                            part += fmaf(-0.0625f, sqrtf(Dc), 1.0f) * g_q[j];
                    } else if (bb == B2) {
                        float w = (pid[j] != s_pidc[c])
                                  ? fmaf(-0.0625f, sqrtf(Dc), 1.0f) * g_q[j] : 0.0f;
                        int p = atomicAdd(&s_bcnt, 1);
                        if (p < CAPW) {
                            s_bk[c][0][p] = __float_as_uint(Dc);
                            s_bj[c][1][p] = __float_as_int(w);
                        }
                    }
                }
            }
            __syncthreads();
            int mm = min(s_bcnt, CAPW);
            int r  = KSEL2 - s_cumb;
            if (r > 0) {
                for (int e = tid; e < mm; e += RT) {
                    unsigned ke = s_bk[c][0][e];
                    int rank = 0;
                    for (int k = 0; k < mm; k++) {
                        unsigned kk = s_bk[c][0][k];
                        rank += (kk < ke) || (kk == ke && k < e);
                    }
                    if (rank < r) part += __int_as_float(s_bj[c][1][e]);
                }
            }
        } else {
            // ===== normal path: select among appended candidates =====
            // recompute keys + candidate histogram
            for (int w = 0; w < NW; w++) {
                int cw = s_cnt[c][w];
                for (int e = tid; e < cw; e += RT) {
                    int j = s_bj[c][w][e];
                    float4 a0 = g_xp[2 * j + 0];
                    float4 a1 = g_xp[2 * j + 1];
                    float n2a = g_n2[j];
                    D2_CHAIN(D2, a0, a1, n2a, c)
                    float Dc = fmaxf(D2, 0.0f);
                    s_bk[c][w][e] = __float_as_uint(Dc);
                    atomicAdd(&s_hist[c][min((int)Dc, NBINS - 1)], 1);
                }
            }
            __syncthreads();
            if (tid == 0) {
                int cum = 0, B2 = NBINS, cb = 0;
                for (int b = 0; b < NBINS; b++) {
                    int nc = cum + s_hist[c][b];
                    if (nc >= KSEL2) { B2 = b; cb = cum; break; }
                    cum = nc;
                }
                s_B2 = B2; s_cumb = cb;
            }
            __syncthreads();
            int B2 = s_B2, cumb = s_cumb;
            for (int w = 0; w < NW; w++) {
                int cw = s_cnt[c][w];
                for (int e = tid; e < cw; e += RT) {
                    unsigned key = s_bk[c][w][e];
                    float kf = __uint_as_float(key);
                    int bin = (int)kf;
                    bool sel = (bin < B2);
                    if (bin == B2) {
                        int gidx = w * CAPW + e;
                        int rank = cumb;
                        for (int w2 = 0; w2 < NW; w2++) {
                            int cw2 = s_cnt[c][w2];
                            for (int k2 = 0; k2 < cw2; k2++) {
                                unsigned kk = s_bk[c][w2][k2];
                                if ((int)__uint_as_float(kk) == B2) {
                                    int g2 = w2 * CAPW + k2;
                                    rank += (kk < key) || (kk == key && g2 < gidx);
                                }
                            }
                        }
                        sel = (rank < KSEL2);
                    }
                    if (sel) {
                        int j = s_bj[c][w][e];
                        if (pid[j] != s_pidc[c])
                            part += fmaf(-0.0625f, sqrtf(kf), 1.0f) * g_q[j];
                    }
                }
            }
        }

        // block reduction + accumulate
        #pragma unroll
        for (int o = 16; o; o >>= 1) part += __shfl_down_sync(0xFFFFFFFFu, part, o);
        if (lane == 0) s_red[wid] = part;
        __syncthreads();
        if (tid == 0) {
            float tot = 0.0f;
            #pragma unroll
            for (int w = 0; w < NW; w++) tot += s_red[w];
            if (tot != 0.0f) atomicAdd(&g_rep, (double)(tot * s_qc[c]));
        }
        __syncthreads();
    }
}

__global__ void k_final(float* out, int N) {
    if (blockIdx.x == 0 && threadIdx.x == 0) {
        int mc = g_maskcnt;
        out[0] = (float)(mc > 0 ? g_att / (double)mc : 0.0);
        out[1] = (float)(g_rep / (double)N);
        out[2] = 0.0f;
        out[3] = 0.0f;
    }
}

extern "C" void kernel_launch(void* const* d_in, const int* in_sizes, int n_in,
                              void* d_out, int out_size) {
    const float* beta  = (const float*)d_in[0];
    const float* x     = (const float*)d_in[1];
    const int*   pid   = (const int*)d_in[2];
    const int*   recon = (const int*)d_in[3];
    const float* pt    = (const float*)d_in[4];
    const float* eta   = (const float*)d_in[5];
    float* out = (float*)d_out;
    int N = in_sizes[0];

    k_init<<<(NPIDMAX + 255) / 256, 256>>>();
    k_bestq<<<(N + 255) / 256, 256>>>(beta, pid, x, N);
    k_attract<<<(N + 127) / 128, 128>>>(x, pid, recon, pt, eta, N);
    int ngrp = (NPIDMAX + CPT - 1) / CPT;   // 512 blocks
    k_repulse<<<ngrp, RT>>>(pid, N);
    k_final<<<1, 32>>>(out, N);
}

// round 14
// speedup vs baseline: 2.3355x; 2.3355x over previous
#include <cuda_runtime.h>
#include <math.h>

// Fixed-shape problem: N=16384, D=8, pid in [0,2000), K=128, R=1
#define NMAX    16384
#define NPIDMAX 2048
#define KSEL2   129     // top-(K+1) including self (self weight = 0)
#define CPT     4       // condensation points per repulsion block
#define RT      256     // threads per block
#define NB      256     // histogram bins over D2=256*d2
#define BCAP    128     // boundary-bin candidate capacity per CP

// -------- device scratch (small, allocation-free) --------
__device__ unsigned long long g_best[NPIDMAX];
__device__ float  g_q[NMAX];
__device__ float  g_n2[NMAX];
__device__ float4 g_xp[NMAX * 2];
__device__ int    g_cplist[NPIDMAX];
__device__ int    g_cpcount;
__device__ double g_att;
__device__ double g_rep;
__device__ int    g_maskcnt;

// predicated shared histogram increment (R9-proven light form)
__device__ __forceinline__ void hist_add(unsigned smem_addr, float D2) {
    asm volatile(
        "{\n\t.reg .pred p;\n\t"
        "setp.le.f32 p, %1, 0f43800000;\n\t"   // D2 <= 256.0f
        "@p red.shared.add.u32 [%0], 1;\n\t}"
        :: "r"(smem_addr), "f"(D2) : "memory");
}

__global__ void k_init() {
    int i = blockIdx.x * blockDim.x + threadIdx.x;
    if (i < NPIDMAX) g_best[i] = 0ULL;
    if (i == 0) { g_cpcount = 0; g_att = 0.0; g_rep = 0.0; g_maskcnt = 0; }
}

__global__ void k_bestq(const float* __restrict__ beta, const int* __restrict__ pid,
                        const float* __restrict__ x, int N) {
    int i = blockIdx.x * blockDim.x + threadIdx.x;
    if (i >= N) return;
    float b = beta[i];
    float t = atanhf(b);
    g_q[i] = t * t + 0.01f;
    float4 v0 = *(const float4*)(x + (size_t)i * 8);
    float4 v1 = *(const float4*)(x + (size_t)i * 8 + 4);
    float n2 = v0.x * v0.x + v0.y * v0.y + v0.z * v0.z + v0.w * v0.w
             + v1.x * v1.x + v1.y * v1.y + v1.z * v1.z + v1.w * v1.w;
    g_n2[i] = n2;
    g_xp[2 * i + 0] = v0;
    g_xp[2 * i + 1] = v1;
    int p = pid[i];
    if (p > 0 && p < NPIDMAX) {
        unsigned long long key =
            ((unsigned long long)__float_as_uint(b) << 32) |
            (unsigned long long)(0xFFFFFFFFu - (unsigned)i);
        atomicMax(&g_best[p], key);
    }
}

__global__ void k_attract(const float* __restrict__ x, const int* __restrict__ pid,
                          const int* __restrict__ recon, const float* __restrict__ pt,
                          const float* __restrict__ eta, int N) {
    int i = blockIdx.x * blockDim.x + threadIdx.x;
    if (i > 0 && i < NPIDMAX) {
        unsigned long long key = g_best[i];
        if (key != 0ULL) {
            int idx = (int)(0xFFFFFFFFu - (unsigned)(key & 0xFFFFFFFFull));
            int pos = atomicAdd(&g_cpcount, 1);
            g_cplist[pos] = idx;
        }
    }
    float va = 0.0f; int m = 0;
    if (i < N) {
        int p = pid[i];
        if (p > 0 && pt[i] > 0.9f && recon[i] > 0 && fabsf(eta[i]) < 4.0f) {
            unsigned long long key = g_best[p];
            int a = (int)(0xFFFFFFFFu - (unsigned)(key & 0xFFFFFFFFull));
            const float4* xi = (const float4*)(x + (size_t)i * 8);
            const float4* xa = (const float4*)(x + (size_t)a * 8);
            float4 i0 = xi[0], i1 = xi[1], a0 = xa[0], a1 = xa[1];
            float d, d2 = 0.0f;
            d = i0.x - a0.x; d2 += d * d;
            d = i0.y - a0.y; d2 += d * d;
            d = i0.z - a0.z; d2 += d * d;
            d = i0.w - a0.w; d2 += d * d;
            d = i1.x - a1.x; d2 += d * d;
            d = i1.y - a1.y; d2 += d * d;
            d = i1.z - a1.z; d2 += d * d;
            d = i1.w - a1.w; d2 += d * d;
            va = d2 * g_q[i] * g_q[a];
            m = 1;
        }
    }
    #pragma unroll
    for (int o = 16; o; o >>= 1) {
        va += __shfl_down_sync(0xFFFFFFFFu, va, o);
        m  += __shfl_down_sync(0xFFFFFFFFu, m,  o);
    }
    if ((threadIdx.x & 31) == 0 && (m || va != 0.0f)) {
        atomicAdd(&g_att, (double)va);
        atomicAdd(&g_maskcnt, m);
    }
}

// scaled distance chain: D2 = 256*d2 (m2x = -512*xc, n2cs = 256*|xc|^2)
// identical expression in both passes -> bit-identical classification
#define D2_CHAIN(res, V0, V1, N2J, c)                 \
    float res = fmaf(V0.x, m2x[c][0], n2cs[c]);       \
    res = fmaf(V0.y, m2x[c][1], res);                 \
    res = fmaf(V0.z, m2x[c][2], res);                 \
    res = fmaf(V0.w, m2x[c][3], res);                 \
    res = fmaf(V1.x, m2x[c][4], res);                 \
    res = fmaf(V1.y, m2x[c][5], res);                 \
    res = fmaf(V1.z, m2x[c][6], res);                 \
    res = fmaf(V1.w, m2x[c][7], res);                 \
    res = fmaf(N2J, 256.0f, res);

// ---- repulsion: R9 structure, slimmed per-pair arithmetic ----
__global__ void __launch_bounds__(RT, 4) k_repulse(const int* __restrict__ pid, int N) {
    __shared__ int      s_hist[CPT][NB];
    __shared__ int      s_Bs[CPT];
    __shared__ int      s_rs[CPT];
    __shared__ int      s_bcnt[CPT];
    __shared__ unsigned s_bk[CPT][BCAP];
    __shared__ float    s_bw[CPT][BCAP];
    __shared__ float    s_qc[CPT];
    __shared__ float    s_red[RT / 32];

    int tid   = threadIdx.x;
    int ncp   = g_cpcount;
    int cbase = blockIdx.x * CPT;
    if (cbase >= ncp) return;

    float m2x[CPT][8], n2cs[CPT];
    int   pidc[CPT];
    #pragma unroll
    for (int c = 0; c < CPT; c++) {
        int slot = cbase + c;
        bool act = slot < ncp;
        int ci = act ? g_cplist[slot] : 0;
        float4 p0 = g_xp[2 * ci + 0];
        float4 p1 = g_xp[2 * ci + 1];
        m2x[c][0] = -512.0f * p0.x; m2x[c][1] = -512.0f * p0.y;
        m2x[c][2] = -512.0f * p0.z; m2x[c][3] = -512.0f * p0.w;
        m2x[c][4] = -512.0f * p1.x; m2x[c][5] = -512.0f * p1.y;
        m2x[c][6] = -512.0f * p1.z; m2x[c][7] = -512.0f * p1.w;
        n2cs[c] = act ? 256.0f * g_n2[ci] : 1e30f;
        pidc[c] = act ? pid[ci]  : -1;
        if (tid == 0) s_qc[c] = act ? g_q[ci] : 0.0f;
    }

    for (int h = tid; h < CPT * NB; h += RT) ((int*)s_hist)[h] = 0;
    if (tid < CPT) s_bcnt[tid] = 0;
    __syncthreads();

    unsigned histbase[CPT];
    #pragma unroll
    for (int c = 0; c < CPT; c++)
        histbase[c] = (unsigned)__cvta_generic_to_shared(&s_hist[c][0]);

    // ---- Pass A: branchless count histogram ----
    for (int j = tid; j < N; j += RT) {
        float4 v0 = g_xp[2 * j + 0];
        float4 v1 = g_xp[2 * j + 1];
        float n2j = g_n2[j];
        #pragma unroll
        for (int c = 0; c < CPT; c++) {
            D2_CHAIN(D2, v0, v1, n2j, c)
            int bb = min((int)fmaxf(D2, 0.0f), NB - 1);
            hist_add(histbase[c] + (unsigned)(bb << 2), D2);
        }
    }
    __syncthreads();

    // ---- selection: boundary bin B and residual r per CP ----
    if (tid < CPT) {
        int cum = 0, B = NB, r = 0;
        for (int b = 0; b < NB; b++) {
            int nc = cum + s_hist[tid][b];
            if (nc >= KSEL2) { B = b; r = KSEL2 - cum; break; }
            cum = nc;
        }
        s_Bs[tid] = B; s_rs[tid] = r;
    }
    __syncthreads();

    float Bf[CPT]; int Breg[CPT];
    #pragma unroll
    for (int c = 0; c < CPT; c++) { Breg[c] = s_Bs[c]; Bf[c] = (float)s_Bs[c]; }

    // ---- Pass B: float-compare classification; predicated accumulate ----
    float acc[CPT];
    #pragma unroll
    for (int c = 0; c < CPT; c++) acc[c] = 0.0f;

    for (int j = tid; j < N; j += RT) {
        float4 v0 = g_xp[2 * j + 0];
        float4 v1 = g_xp[2 * j + 1];
        float n2j = g_n2[j];
        float qj  = g_q[j];
        int   pj  = pid[j];
        bool anyB = false;
        float ds[CPT];
        #pragma unroll
        for (int c = 0; c < CPT; c++) {
            D2_CHAIN(D2, v0, v1, n2j, c)
            ds[c] = D2;
            // bin < B  <=>  max(D2,0) < Bf  <=>  D2 < Bf   (Bf >= 0)
            float w = fmaf(-0.0625f, sqrtf(fmaxf(D2, 0.0f)), 1.0f) * qj;
            bool sel = (D2 < Bf[c]) && (pj != pidc[c]);
            acc[c] += sel ? w : 0.0f;
            anyB |= (D2 >= Bf[c]) && (D2 <= 256.0f);
        }
        if (__any_sync(0xFFFFFFFFu, anyB)) {
            #pragma unroll
            for (int c = 0; c < CPT; c++) {
                float D2 = ds[c];
                if (D2 >= Bf[c] && D2 <= 256.0f) {
                    float Dc = fmaxf(D2, 0.0f);
                    int bb = min((int)Dc, NB - 1);       // exact bin, cold path
                    if (bb == Breg[c]) {
                        float w = (pj != pidc[c])
                                  ? fmaf(-0.0625f, sqrtf(Dc), 1.0f) * qj : 0.0f;
                        int p = atomicAdd(&s_bcnt[c], 1);
                        if (p < BCAP) { s_bk[c][p] = __float_as_uint(Dc); s_bw[c][p] = w; }
                    }
                }
            }
        }
    }
    __syncthreads();

    // ---- boundary mini-rank + per-CP reduction ----
    #pragma unroll
    for (int c = 0; c < CPT; c++) {
        float part = acc[c];
        int m = min(s_bcnt[c], BCAP);
        int r = s_rs[c];
        if (r > 0) {
            for (int e = tid; e < m; e += RT) {
                unsigned ke = s_bk[c][e];
                int rank = 0;
                for (int k = 0; k < m; k++) {
                    unsigned kk = s_bk[c][k];
                    rank += (kk < ke) || (kk == ke && k < e);
                }
                if (rank < r) part += s_bw[c][e];
            }
        }
        #pragma unroll
        for (int o = 16; o; o >>= 1) part += __shfl_down_sync(0xFFFFFFFFu, part, o);
        if ((tid & 31) == 0) s_red[tid >> 5] = part;
        __syncthreads();
        if (tid == 0) {
            float tot = 0.0f;
            #pragma unroll
            for (int w = 0; w < RT / 32; w++) tot += s_red[w];
            if (tot != 0.0f) atomicAdd(&g_rep, (double)(tot * s_qc[c]));
        }
        __syncthreads();
    }
}

__global__ void k_final(float* out, int N) {
    if (blockIdx.x == 0 && threadIdx.x == 0) {
        int mc = g_maskcnt;
        out[0] = (float)(mc > 0 ? g_att / (double)mc : 0.0);
        out[1] = (float)(g_rep / (double)N);
        out[2] = 0.0f;
        out[3] = 0.0f;
    }
}

extern "C" void kernel_launch(void* const* d_in, const int* in_sizes, int n_in,
                              void* d_out, int out_size) {
    const float* beta  = (const float*)d_in[0];
    const float* x     = (const float*)d_in[1];
    const int*   pid   = (const int*)d_in[2];
    const int*   recon = (const int*)d_in[3];
    const float* pt    = (const float*)d_in[4];
    const float* eta   = (const float*)d_in[5];
    float* out = (float*)d_out;
    int N = in_sizes[0];

    k_init<<<(NPIDMAX + 255) / 256, 256>>>();
    k_bestq<<<(N + 255) / 256, 256>>>(beta, pid, x, N);
    k_attract<<<(N + 127) / 128, 128>>>(x, pid, recon, pt, eta, N);
    int ngrp = (NPIDMAX + CPT - 1) / CPT;   // 512 blocks
    k_repulse<<<ngrp, RT>>>(pid, N);
    k_final<<<1, 32>>>(out, N);
}

// round 15
// speedup vs baseline: 2.3804x; 1.0192x over previous
#include <cuda_runtime.h>
#include <math.h>

// Fixed-shape problem: N=16384, D=8, pid in [0,2000), K=128, R=1
#define NMAX    16384
#define NPIDMAX 2048
#define KSEL2   129     // top-(K+1) including self (self weight = 0)
#define CPT     4       // condensation points per repulsion block
#define RT      256     // threads per block
#define NB      256     // histogram bins over D2=256*d2
#define BCAP    128     // boundary-bin candidate capacity per CP

// -------- device scratch (small, allocation-free) --------
__device__ unsigned long long g_best[NPIDMAX];
__device__ float  g_q[NMAX];
__device__ float4 g_pack[NMAX * 3];   // {x0..3},{x4..7},{n2,q,pid,0}
__device__ int    g_cplist[NPIDMAX];
__device__ int    g_cpcount;
__device__ double g_att;
__device__ double g_rep;
__device__ int    g_maskcnt;

// predicated shared histogram increment (R9-proven light form)
__device__ __forceinline__ void hist_add(unsigned smem_addr, float D2) {
    asm volatile(
        "{\n\t.reg .pred p;\n\t"
        "setp.le.f32 p, %1, 0f43800000;\n\t"   // D2 <= 256.0f
        "@p red.shared.add.u32 [%0], 1;\n\t}"
        :: "r"(smem_addr), "f"(D2) : "memory");
}

__global__ void k_init() {
    int i = blockIdx.x * blockDim.x + threadIdx.x;
    if (i < NPIDMAX) g_best[i] = 0ULL;
    if (i == 0) { g_cpcount = 0; g_att = 0.0; g_rep = 0.0; g_maskcnt = 0; }
}

__global__ void k_bestq(const float* __restrict__ beta, const int* __restrict__ pid,
                        const float* __restrict__ x, int N) {
    int i = blockIdx.x * blockDim.x + threadIdx.x;
    if (i >= N) return;
    float b = beta[i];
    float t = atanhf(b);
    float q = t * t + 0.01f;
    g_q[i] = q;
    float4 v0 = *(const float4*)(x + (size_t)i * 8);
    float4 v1 = *(const float4*)(x + (size_t)i * 8 + 4);
    float n2 = v0.x * v0.x + v0.y * v0.y + v0.z * v0.z + v0.w * v0.w
             + v1.x * v1.x + v1.y * v1.y + v1.z * v1.z + v1.w * v1.w;
    int p = pid[i];
    g_pack[3 * i + 0] = v0;
    g_pack[3 * i + 1] = v1;
    g_pack[3 * i + 2] = make_float4(n2, q, __int_as_float(p), 0.0f);
    if (p > 0 && p < NPIDMAX) {
        unsigned long long key =
            ((unsigned long long)__float_as_uint(b) << 32) |
            (unsigned long long)(0xFFFFFFFFu - (unsigned)i);
        atomicMax(&g_best[p], key);
    }
}

__global__ void k_attract(const float* __restrict__ x, const int* __restrict__ pid,
                          const int* __restrict__ recon, const float* __restrict__ pt,
                          const float* __restrict__ eta, int N) {
    int i = blockIdx.x * blockDim.x + threadIdx.x;
    if (i > 0 && i < NPIDMAX) {
        unsigned long long key = g_best[i];
        if (key != 0ULL) {
            int idx = (int)(0xFFFFFFFFu - (unsigned)(key & 0xFFFFFFFFull));
            int pos = atomicAdd(&g_cpcount, 1);
            g_cplist[pos] = idx;
        }
    }
    float va = 0.0f; int m = 0;
    if (i < N) {
        int p = pid[i];
        if (p > 0 && pt[i] > 0.9f && recon[i] > 0 && fabsf(eta[i]) < 4.0f) {
            unsigned long long key = g_best[p];
            int a = (int)(0xFFFFFFFFu - (unsigned)(key & 0xFFFFFFFFull));
            const float4* xi = (const float4*)(x + (size_t)i * 8);
            const float4* xa = (const float4*)(x + (size_t)a * 8);
            float4 i0 = xi[0], i1 = xi[1], a0 = xa[0], a1 = xa[1];
            float d, d2 = 0.0f;
            d = i0.x - a0.x; d2 += d * d;
            d = i0.y - a0.y; d2 += d * d;
            d = i0.z - a0.z; d2 += d * d;
            d = i0.w - a0.w; d2 += d * d;
            d = i1.x - a1.x; d2 += d * d;
            d = i1.y - a1.y; d2 += d * d;
            d = i1.z - a1.z; d2 += d * d;
            d = i1.w - a1.w; d2 += d * d;
            va = d2 * g_q[i] * g_q[a];
            m = 1;
        }
    }
    #pragma unroll
    for (int o = 16; o; o >>= 1) {
        va += __shfl_down_sync(0xFFFFFFFFu, va, o);
        m  += __shfl_down_sync(0xFFFFFFFFu, m,  o);
    }
    if ((threadIdx.x & 31) == 0 && (m || va != 0.0f)) {
        atomicAdd(&g_att, (double)va);
        atomicAdd(&g_maskcnt, m);
    }
}

// scaled distance chain: D2 = 256*d2 (m2x = -512*xc, n2cs = 256*|xc|^2)
// identical expression in both passes -> bit-identical classification
#define D2_CHAIN(res, V0, V1, N2J, c)                 \
    float res = fmaf(V0.x, m2x[c][0], n2cs[c]);       \
    res = fmaf(V0.y, m2x[c][1], res);                 \
    res = fmaf(V0.z, m2x[c][2], res);                 \
    res = fmaf(V0.w, m2x[c][3], res);                 \
    res = fmaf(V1.x, m2x[c][4], res);                 \
    res = fmaf(V1.y, m2x[c][5], res);                 \
    res = fmaf(V1.z, m2x[c][6], res);                 \
    res = fmaf(V1.w, m2x[c][7], res);                 \
    res = fmaf(N2J, 256.0f, res);

// ---- repulsion: R14 structure, packed 3xfloat4 j-stream ----
__global__ void __launch_bounds__(RT, 4) k_repulse(int N) {
    __shared__ int      s_hist[CPT][NB];
    __shared__ int      s_Bs[CPT];
    __shared__ int      s_rs[CPT];
    __shared__ int      s_bcnt[CPT];
    __shared__ unsigned s_bk[CPT][BCAP];
    __shared__ float    s_bw[CPT][BCAP];
    __shared__ float    s_qc[CPT];
    __shared__ float    s_red[RT / 32];

    int tid   = threadIdx.x;
    int ncp   = g_cpcount;
    int cbase = blockIdx.x * CPT;
    if (cbase >= ncp) return;

    float m2x[CPT][8], n2cs[CPT];
    int   pidc[CPT];
    #pragma unroll
    for (int c = 0; c < CPT; c++) {
        int slot = cbase + c;
        bool act = slot < ncp;
        int ci = act ? g_cplist[slot] : 0;
        float4 p0 = g_pack[3 * ci + 0];
        float4 p1 = g_pack[3 * ci + 1];
        float4 p2 = g_pack[3 * ci + 2];
        m2x[c][0] = -512.0f * p0.x; m2x[c][1] = -512.0f * p0.y;
        m2x[c][2] = -512.0f * p0.z; m2x[c][3] = -512.0f * p0.w;
        m2x[c][4] = -512.0f * p1.x; m2x[c][5] = -512.0f * p1.y;
        m2x[c][6] = -512.0f * p1.z; m2x[c][7] = -512.0f * p1.w;
        n2cs[c] = act ? 256.0f * p2.x : 1e30f;
        pidc[c] = act ? __float_as_int(p2.z) : -1;
        if (tid == 0) s_qc[c] = act ? p2.y : 0.0f;
    }

    for (int h = tid; h < CPT * NB; h += RT) ((int*)s_hist)[h] = 0;
    if (tid < CPT) s_bcnt[tid] = 0;
    __syncthreads();

    unsigned histbase[CPT];
    #pragma unroll
    for (int c = 0; c < CPT; c++)
        histbase[c] = (unsigned)__cvta_generic_to_shared(&s_hist[c][0]);

    // ---- Pass A: branchless count histogram ----
    for (int j = tid; j < N; j += RT) {
        float4 v0 = g_pack[3 * j + 0];
        float4 v1 = g_pack[3 * j + 1];
        float4 v2 = g_pack[3 * j + 2];
        float n2j = v2.x;
        #pragma unroll
        for (int c = 0; c < CPT; c++) {
            D2_CHAIN(D2, v0, v1, n2j, c)
            int bb = min((int)fmaxf(D2, 0.0f), NB - 1);
            hist_add(histbase[c] + (unsigned)(bb << 2), D2);
        }
    }
    __syncthreads();

    // ---- selection: boundary bin B and residual r per CP ----
    if (tid < CPT) {
        int cum = 0, B = NB, r = 0;
        for (int b = 0; b < NB; b++) {
            int nc = cum + s_hist[tid][b];
            if (nc >= KSEL2) { B = b; r = KSEL2 - cum; break; }
            cum = nc;
        }
        s_Bs[tid] = B; s_rs[tid] = r;
    }
    __syncthreads();

    float Bf[CPT]; int Breg[CPT];
    #pragma unroll
    for (int c = 0; c < CPT; c++) { Breg[c] = s_Bs[c]; Bf[c] = (float)s_Bs[c]; }

    // ---- Pass B: float-compare classification; predicated accumulate ----
    float acc[CPT];
    #pragma unroll
    for (int c = 0; c < CPT; c++) acc[c] = 0.0f;

    for (int j = tid; j < N; j += RT) {
        float4 v0 = g_pack[3 * j + 0];
        float4 v1 = g_pack[3 * j + 1];
        float4 v2 = g_pack[3 * j + 2];
        float n2j = v2.x;
        float qj  = v2.y;
        int   pj  = __float_as_int(v2.z);
        bool anyB = false;
        float ds[CPT];
        #pragma unroll
        for (int c = 0; c < CPT; c++) {
            D2_CHAIN(D2, v0, v1, n2j, c)
            ds[c] = D2;
            float w = fmaf(-0.0625f, sqrtf(fmaxf(D2, 0.0f)), 1.0f) * qj;
            bool sel = (D2 < Bf[c]) && (pj != pidc[c]);
            acc[c] += sel ? w : 0.0f;
            anyB |= (D2 >= Bf[c]) && (D2 <= 256.0f);
        }
        if (__any_sync(0xFFFFFFFFu, anyB)) {
            #pragma unroll
            for (int c = 0; c < CPT; c++) {
                float D2 = ds[c];
                if (D2 >= Bf[c] && D2 <= 256.0f) {
                    float Dc = fmaxf(D2, 0.0f);
                    int bb = min((int)Dc, NB - 1);       // exact bin, cold path
                    if (bb == Breg[c]) {
                        float w = (pj != pidc[c])
                                  ? fmaf(-0.0625f, sqrtf(Dc), 1.0f) * qj : 0.0f;
                        int p = atomicAdd(&s_bcnt[c], 1);
                        if (p < BCAP) { s_bk[c][p] = __float_as_uint(Dc); s_bw[c][p] = w; }
                    }
                }
            }
        }
    }
    __syncthreads();

    // ---- boundary mini-rank + per-CP reduction ----
    #pragma unroll
    for (int c = 0; c < CPT; c++) {
        float part = acc[c];
        int m = min(s_bcnt[c], BCAP);
        int r = s_rs[c];
        if (r > 0) {
            for (int e = tid; e < m; e += RT) {
                unsigned ke = s_bk[c][e];
                int rank = 0;
                for (int k = 0; k < m; k++) {
                    unsigned kk = s_bk[c][k];
                    rank += (kk < ke) || (kk == ke && k < e);
                }
                if (rank < r) part += s_bw[c][e];
            }
        }
        #pragma unroll
        for (int o = 16; o; o >>= 1) part += __shfl_down_sync(0xFFFFFFFFu, part, o);
        if ((tid & 31) == 0) s_red[tid >> 5] = part;
        __syncthreads();
        if (tid == 0) {
            float tot = 0.0f;
            #pragma unroll
            for (int w = 0; w < RT / 32; w++) tot += s_red[w];
            if (tot != 0.0f) atomicAdd(&g_rep, (double)(tot * s_qc[c]));
        }
        __syncthreads();
    }
}

__global__ void k_final(float* out, int N) {
    if (blockIdx.x == 0 && threadIdx.x == 0) {
        int mc = g_maskcnt;
        out[0] = (float)(mc > 0 ? g_att / (double)mc : 0.0);
        out[1] = (float)(g_rep / (double)N);
        out[2] = 0.0f;
        out[3] = 0.0f;
    }
}

extern "C" void kernel_launch(void* const* d_in, const int* in_sizes, int n_in,
                              void* d_out, int out_size) {
    const float* beta  = (const float*)d_in[0];
    const float* x     = (const float*)d_in[1];
    const int*   pid   = (const int*)d_in[2];
    const int*   recon = (const int*)d_in[3];
    const float* pt    = (const float*)d_in[4];
    const float* eta   = (const float*)d_in[5];
    float* out = (float*)d_out;
    int N = in_sizes[0];

    k_init<<<(NPIDMAX + 255) / 256, 256>>>();
    k_bestq<<<(N + 255) / 256, 256>>>(beta, pid, x, N);
    k_attract<<<(N + 127) / 128, 128>>>(x, pid, recon, pt, eta, N);
    int ngrp = (NPIDMAX + CPT - 1) / CPT;   // 512 blocks
    k_repulse<<<ngrp, RT>>>(N);
    k_final<<<1, 32>>>(out, N);
}